// round 7
// baseline (speedup 1.0000x reference)
#include <cuda_runtime.h>

// CenterLoss collapses algebraically: after masking, only the true-label
// column survives; the other C-1 zeros clamp to 1e-12 each.
//   loss = sum_n clamp(||x_n - c_{lab_n}||^2, 1e-12, 1e12) + N*(C-1)*1e-12
//
// R7: serial-depth reduction. Evidence (R4-R6): dur insensitive to occupancy
// and MLP -> latency-chain dominated. Changes vs R6:
//  - per-warp label fetch (lane0 LDG + shfl): no syncthreads before gather
//  - label LDG issued first; x LDGs fly during its latency; center LDGs after
//  - last-CTA tail reads partials as float4 (one vector round trip)
// Shape kept from R6: 1024 CTAs x 256 threads, half-row per warp, 4 LDG.128
// per lane. Fixed-order reductions everywhere -> deterministic.

#define N_ROWS 4096      // 16 * 256
#define FEAT_DIM 512
#define F4_PER_ROW (FEAT_DIM / 4)   // 128
#define NUM_CLASSES 10000
#define NUM_CTAS 1024
#define ROWS_PER_CTA 4

__device__ float g_cta_partials[NUM_CTAS];
__device__ unsigned int g_done_count = 0;

__global__ __launch_bounds__(256, 8) void center_loss_kernel(
    const float* __restrict__ x,
    const int* __restrict__ labels,
    const float* __restrict__ centers,
    float* __restrict__ out)
{
    const int t = threadIdx.x;
    const int warp = t >> 5;          // 0..7
    const int lane = t & 31;
    const int cta = blockIdx.x;
    const int lrow = warp >> 1;       // 0..3 local row
    const int half = warp & 1;        // 0..1 half of the row

    const int row = cta * ROWS_PER_CTA + lrow;

    __shared__ float s_half[8];
    __shared__ bool s_is_last;

    // 1) Label load first (head of the longest dependent chain).
    int c = 0;
    if (lane == 0) c = labels[row];

    // 2) x loads: independent, overlap the label latency.
    const float4* __restrict__ xr =
        reinterpret_cast<const float4*>(x) + (size_t)row * F4_PER_ROW + half * 64;
    float4 a0 = xr[lane];
    float4 a1 = xr[32 + lane];

    // 3) Broadcast label, then the dependent center gather.
    c = __shfl_sync(0xffffffffu, c, 0);
    c = min(max(c, 0), NUM_CLASSES - 1);

    const float4* __restrict__ cr =
        reinterpret_cast<const float4*>(centers) + (size_t)c * F4_PER_ROW + half * 64;
    float4 b0 = cr[lane];
    float4 b1 = cr[32 + lane];

    float d0 = a0.x - b0.x, d1 = a0.y - b0.y, d2 = a0.z - b0.z, d3 = a0.w - b0.w;
    float s = d0 * d0 + d1 * d1 + d2 * d2 + d3 * d3;
    d0 = a1.x - b1.x; d1 = a1.y - b1.y; d2 = a1.z - b1.z; d3 = a1.w - b1.w;
    s += d0 * d0 + d1 * d1 + d2 * d2 + d3 * d3;

    // warp reduce -> lane 0 holds half-row sum
    #pragma unroll
    for (int o = 16; o > 0; o >>= 1)
        s += __shfl_xor_sync(0xffffffffu, s, o);

    if (lane == 0) s_half[warp] = s;
    __syncthreads();

    if (t == 0) {
        float acc = 0.0f;
        #pragma unroll
        for (int r = 0; r < ROWS_PER_CTA; r++) {
            float rs = s_half[2 * r] + s_half[2 * r + 1];
            rs = fminf(fmaxf(rs, 1e-12f), 1e12f);   // per-row clamp
            acc += rs;
        }
        g_cta_partials[cta] = acc;
        __threadfence();
        unsigned int v = atomicAdd(&g_done_count, 1u);
        s_is_last = (v == (unsigned int)(NUM_CTAS - 1));
    }
    __syncthreads();

    if (s_is_last) {
        // 1024 partials as 256 float4: one vector load per thread.
        float4 p = reinterpret_cast<const float4*>(g_cta_partials)[t];
        float v = (p.x + p.y) + (p.z + p.w);

        #pragma unroll
        for (int o = 16; o > 0; o >>= 1)
            v += __shfl_xor_sync(0xffffffffu, v, o);

        __shared__ float fs[8];
        if (lane == 0) fs[warp] = v;
        __syncthreads();

        if (t == 0) {
            const float zero_clamp_sum =
                (float)((double)N_ROWS * (double)(NUM_CLASSES - 1) * 1e-12);
            float r = 0.0f;
            #pragma unroll
            for (int w = 0; w < 8; w++) r += fs[w];
            out[0] = r + zero_clamp_sum;
            g_done_count = 0;   // reset for next graph replay
        }
    }
}

extern "C" void kernel_launch(void* const* d_in, const int* in_sizes, int n_in,
                              void* d_out, int out_size)
{
    const float* x       = (const float*)d_in[0];  // (16,256,512) f32
    const int*   labels  = (const int*)d_in[1];    // (16,256) int32
    const float* centers = (const float*)d_in[2];  // (10000,512) f32
    float*       out     = (float*)d_out;          // scalar

    (void)in_sizes; (void)n_in; (void)out_size;

    center_loss_kernel<<<NUM_CTAS, 256>>>(x, labels, centers, out);
}

// round 8
// speedup vs baseline: 1.0584x; 1.0584x over previous
#include <cuda_runtime.h>

// CenterLoss collapses algebraically: after masking, only the true-label
// column survives; the other C-1 zeros clamp to 1e-12 each.
//   loss = sum_n clamp(||x_n - c_{lab_n}||^2, 1e-12, 1e12) + N*(C-1)*1e-12
//
// R8: attack the L1tex wavefront-replay ceiling. All R4-R7 variants used
// LDG.128 (4 wavefronts/instr, ~2.07 cyc/wf within-LDG replay rate) and all
// pinned at ~1.9 TB/s regardless of occupancy/MLP. Switch data loads to
// float2 (LDG.64, 2 wf/instr, mostly cross-LDG at ~1.0 cyc/wf) -> same
// bytes, ~2x L1tex service rate. Structure otherwise as R7: 1024 CTAs x
// 256 thr, half-row per warp, per-warp label fetch overlapped with x loads,
// fused last-CTA fixed-order tail -> deterministic.

#define N_ROWS 4096      // 16 * 256
#define FEAT_DIM 512
#define F2_PER_ROW (FEAT_DIM / 2)   // 256
#define NUM_CLASSES 10000
#define NUM_CTAS 1024
#define ROWS_PER_CTA 4

__device__ float g_cta_partials[NUM_CTAS];
__device__ unsigned int g_done_count = 0;

__global__ __launch_bounds__(256, 8) void center_loss_kernel(
    const float* __restrict__ x,
    const int* __restrict__ labels,
    const float* __restrict__ centers,
    float* __restrict__ out)
{
    const int t = threadIdx.x;
    const int warp = t >> 5;          // 0..7
    const int lane = t & 31;
    const int cta = blockIdx.x;
    const int lrow = warp >> 1;       // 0..3 local row
    const int half = warp & 1;        // 0..1 half of the row

    const int row = cta * ROWS_PER_CTA + lrow;

    __shared__ float s_half[8];
    __shared__ bool s_is_last;

    // 1) Label load first (head of the longest dependent chain).
    int c = 0;
    if (lane == 0) c = labels[row];

    // 2) x loads (float2 = LDG.64): independent, overlap the label latency.
    const float2* __restrict__ xr =
        reinterpret_cast<const float2*>(x) + (size_t)row * F2_PER_ROW + half * 128;
    float2 a0 = xr[lane];
    float2 a1 = xr[32 + lane];
    float2 a2 = xr[64 + lane];
    float2 a3 = xr[96 + lane];

    // 3) Broadcast label, then the dependent center gather (float2).
    c = __shfl_sync(0xffffffffu, c, 0);
    c = min(max(c, 0), NUM_CLASSES - 1);

    const float2* __restrict__ cr =
        reinterpret_cast<const float2*>(centers) + (size_t)c * F2_PER_ROW + half * 128;
    float2 b0 = cr[lane];
    float2 b1 = cr[32 + lane];
    float2 b2 = cr[64 + lane];
    float2 b3 = cr[96 + lane];

    float d0, d1;
    d0 = a0.x - b0.x; d1 = a0.y - b0.y;
    float s = d0 * d0 + d1 * d1;
    d0 = a1.x - b1.x; d1 = a1.y - b1.y;
    s += d0 * d0 + d1 * d1;
    d0 = a2.x - b2.x; d1 = a2.y - b2.y;
    s += d0 * d0 + d1 * d1;
    d0 = a3.x - b3.x; d1 = a3.y - b3.y;
    s += d0 * d0 + d1 * d1;

    // warp reduce -> lane 0 holds half-row sum
    #pragma unroll
    for (int o = 16; o > 0; o >>= 1)
        s += __shfl_xor_sync(0xffffffffu, s, o);

    if (lane == 0) s_half[warp] = s;
    __syncthreads();

    if (t == 0) {
        float acc = 0.0f;
        #pragma unroll
        for (int r = 0; r < ROWS_PER_CTA; r++) {
            float rs = s_half[2 * r] + s_half[2 * r + 1];
            rs = fminf(fmaxf(rs, 1e-12f), 1e12f);   // per-row clamp
            acc += rs;
        }
        g_cta_partials[cta] = acc;
        __threadfence();
        unsigned int v = atomicAdd(&g_done_count, 1u);
        s_is_last = (v == (unsigned int)(NUM_CTAS - 1));
    }
    __syncthreads();

    if (s_is_last) {
        // 1024 partials as 256 float4: one vector load per thread.
        float4 p = reinterpret_cast<const float4*>(g_cta_partials)[t];
        float v = (p.x + p.y) + (p.z + p.w);

        #pragma unroll
        for (int o = 16; o > 0; o >>= 1)
            v += __shfl_xor_sync(0xffffffffu, v, o);

        __shared__ float fs[8];
        if (lane == 0) fs[warp] = v;
        __syncthreads();

        if (t == 0) {
            const float zero_clamp_sum =
                (float)((double)N_ROWS * (double)(NUM_CLASSES - 1) * 1e-12);
            float r = 0.0f;
            #pragma unroll
            for (int w = 0; w < 8; w++) r += fs[w];
            out[0] = r + zero_clamp_sum;
            g_done_count = 0;   // reset for next graph replay
        }
    }
}

extern "C" void kernel_launch(void* const* d_in, const int* in_sizes, int n_in,
                              void* d_out, int out_size)
{
    const float* x       = (const float*)d_in[0];  // (16,256,512) f32
    const int*   labels  = (const int*)d_in[1];    // (16,256) int32
    const float* centers = (const float*)d_in[2];  // (10000,512) f32
    float*       out     = (float*)d_out;          // scalar

    (void)in_sizes; (void)n_in; (void)out_size;

    center_loss_kernel<<<NUM_CTAS, 256>>>(x, labels, centers, out);
}